// round 7
// baseline (speedup 1.0000x reference)
#include <cuda_runtime.h>
#include <stdint.h>

// Problem constants (fixed shapes from reference)
#define Kc   512               // codebook size
#define Dc   8                 // embedding dim / channels
#define Sc   110592            // 48*48*48
#define Bc   2                 // batch
#define Nc   (Bc * Sc)         // 221184 voxels
#define TPB  384               // threads per block (12 warps)
#define VPB  768               // voxels per block (2 per thread)
#define NBLK (Nc / VPB)        // 288 blocks  (one wave @ 2 CTAs/SM)
#define NPAIR 256              // codebook pairs (Kc/2)
#define O_OUT 1                // out tensor offset (after scalar loss)
#define O_ENC (1 + Nc * Dc)    // encodings offset = 1769473
#define TILE_ENC (VPB * Kc)    // 393216 floats (1.5 MB) per block's tile
#define ZBUF_BYTES 65536       // 64 KB smem zero buffer (TMA source)
#define STG_SLOTS (128 * TPB)  // 49152 float4 = 0.75 MB zeroed by STG path
#define STG_BYTES ((size_t)STG_SLOTS * 16)

// dynamic smem layout
#define SM_ZERO  0
#define SM_EP    (ZBUF_BYTES)                    // 16384 B pair-packed codebook
#define SM_E2    (ZBUF_BYTES + 16384)            // 2048 B entry sums of squares
#define SM_RED   (ZBUF_BYTES + 16384 + 2048)
#define SM_LAST  (SM_RED + 64)
#define SMEM_TOTAL (SM_LAST + 64)

__device__ float    g_sum   = 0.0f;   // reset by last block each run
__device__ unsigned g_count = 0u;

// ---- packed f32x2 helpers (per-lane rounding identical to scalar chain) ----
__device__ __forceinline__ unsigned long long pk2(float lo, float hi) {
    unsigned long long r;
    asm("mov.b64 %0, {%1, %2};" : "=l"(r) : "f"(lo), "f"(hi));
    return r;
}
__device__ __forceinline__ unsigned long long mul2(unsigned long long a, unsigned long long b) {
    unsigned long long d;
    asm("mul.rn.f32x2 %0, %1, %2;" : "=l"(d) : "l"(a), "l"(b));
    return d;
}
__device__ __forceinline__ unsigned long long add2(unsigned long long a, unsigned long long b) {
    unsigned long long d;
    asm("add.rn.f32x2 %0, %1, %2;" : "=l"(d) : "l"(a), "l"(b));
    return d;
}
__device__ __forceinline__ unsigned long long fma2(unsigned long long a, unsigned long long b, unsigned long long c) {
    unsigned long long d;
    asm("fma.rn.f32x2 %0, %1, %2, %3;" : "=l"(d) : "l"(a), "l"(b), "l"(c));
    return d;
}
__device__ __forceinline__ void upk2(unsigned long long v, float& lo, float& hi) {
    asm("mov.b64 {%0, %1}, %2;" : "=f"(lo), "=f"(hi) : "l"(v));
}
__device__ __forceinline__ uint32_t smem_u32(const void* p) {
    uint32_t a;
    asm("{ .reg .u64 t; cvta.to.shared.u64 t, %1; cvt.u32.u64 %0, t; }" : "=r"(a) : "l"(p));
    return a;
}

__global__ __launch_bounds__(TPB, 2) void vq_main_kernel(
    const float* __restrict__ x,
    const float* __restrict__ ew,
    float* __restrict__ out)
{
    extern __shared__ char smem[];
    float4*     sZero = (float4*)(smem + SM_ZERO);
    ulonglong2* sEp   = (ulonglong2*)(smem + SM_EP);   // pair-interleaved codebook
    float*      sE2   = (float*)(smem + SM_E2);
    float*      sRed  = (float*)(smem + SM_RED);
    int*        sLast = (int*)(smem + SM_LAST);

    const int tid = threadIdx.x;

    // ---- Phase 0: fill 64 KB zero buffer (TMA source)
    {
        float4 z4 = make_float4(0.f, 0.f, 0.f, 0.f);
        for (int i = tid; i < ZBUF_BYTES / 16; i += TPB) sZero[i] = z4;
    }

    // ---- Phase 1a: build pair-packed codebook: pair p, coord c -> (e[2p][c], e[2p+1][c])
    {
        float* sf = (float*)sEp;
        for (int idx = tid; idx < NPAIR * Dc; idx += TPB) {
            int p = idx >> 3, c = idx & 7;
            float lo = ew[(2 * p) * Dc + c];
            float hi = ew[(2 * p + 1) * Dc + c];
            int base = p * 16 + (c >> 1) * 4 + (c & 1) * 2;
            sf[base]     = lo;
            sf[base + 1] = hi;
        }
    }
    // ---- Phase 1b: per-entry sum of squares, sequential fp32 (match jnp.sum(e**2))
    for (int k = tid; k < Kc; k += TPB) {
        float4 a = *(const float4*)(ew + (size_t)k * Dc);
        float4 b = *(const float4*)(ew + (size_t)k * Dc + 4);
        float s = __fmul_rn(a.x, a.x);
        s = __fadd_rn(s, __fmul_rn(a.y, a.y));
        s = __fadd_rn(s, __fmul_rn(a.z, a.z));
        s = __fadd_rn(s, __fmul_rn(a.w, a.w));
        s = __fadd_rn(s, __fmul_rn(b.x, b.x));
        s = __fadd_rn(s, __fmul_rn(b.y, b.y));
        s = __fadd_rn(s, __fmul_rn(b.z, b.z));
        s = __fadd_rn(s, __fmul_rn(b.w, b.w));
        sE2[k] = s;
    }
    // Make the generic-proxy smem zero writes visible to the async (TMA) proxy.
    asm volatile("fence.proxy.async.shared::cta;" ::: "memory");
    __syncthreads();

    // ---- Phase 2: hybrid zero-fill of this block's 1.5 MB tile.
    // Front STG_BYTES (0.75 MB): STG.128 interleaved into the argmin loop (LSU path).
    // Back  remainder (0.75 MB): 12 x 64 KB TMA bulk copies (DMA path).
    // The two paths drain to DRAM concurrently.
    float* t0 = out + O_ENC + (size_t)blockIdx.x * TILE_ENC;
    const int head = (int)(((16u - (unsigned)(((uintptr_t)t0) & 15u)) & 15u) >> 2);
    if (tid < head) t0[tid] = 0.0f;                     // peel to 16B alignment
    float4* zv = (float4*)(t0 + head);                  // STG region: slots [0, STG_SLOTS)
    const int nfl = (TILE_ENC - head) & ~3;             // 16B-granular float count
    const size_t tma_bytes = (size_t)nfl * 4 - STG_BYTES;
    if (tid < 8) {
        uint32_t s_addr = smem_u32(sZero);
        char* g = (char*)(t0 + head) + STG_BYTES;
        for (size_t off = (size_t)tid * ZBUF_BYTES; off < tma_bytes;
             off += (size_t)8 * ZBUF_BYTES) {
            unsigned sz = (unsigned)((tma_bytes - off) < (size_t)ZBUF_BYTES
                                     ? (tma_bytes - off) : (size_t)ZBUF_BYTES);
            asm volatile(
                "cp.async.bulk.global.shared::cta.bulk_group [%0], [%1], %2;"
                :: "l"(g + off), "r"(s_addr), "r"(sz) : "memory");
        }
        asm volatile("cp.async.bulk.commit_group;" ::: "memory");
    }
    {   // tail floats not covered by 16B granularity
        int done = head + nfl;
        if (tid < TILE_ENC - done) t0[done + tid] = 0.0f;
    }

    // ---- Phase 3: load this thread's two voxels (strided, warp-coalesced)
    const int bb = (blockIdx.x * VPB) >= Sc ? 1 : 0;    // batch split is block-aligned
    const int n0 = blockIdx.x * VPB + tid;
    const int n1 = n0 + TPB;
    const int sA = n0 - bb * Sc;
    const int sB = n1 - bb * Sc;
    const float* xbase = x + (size_t)bb * (Dc * Sc);

    float xA[8], xB[8];
#pragma unroll
    for (int c = 0; c < 8; c++) {
        xA[c] = xbase[(size_t)c * Sc + sA];
        xB[c] = xbase[(size_t)c * Sc + sB];
    }
    unsigned long long xa[8], xb[8];
#pragma unroll
    for (int c = 0; c < 8; c++) { xa[c] = pk2(xA[c], xA[c]); xb[c] = pk2(xB[c], xB[c]); }

    float s2A = __fmul_rn(xA[0], xA[0]);
    float s2B = __fmul_rn(xB[0], xB[0]);
#pragma unroll
    for (int c = 1; c < 8; c++) {
        s2A = __fadd_rn(s2A, __fmul_rn(xA[c], xA[c]));
        s2B = __fadd_rn(s2B, __fmul_rn(xB[c], xB[c]));
    }
    const unsigned long long sA2 = pk2(s2A, s2A);
    const unsigned long long sB2 = pk2(s2B, s2B);
    const unsigned long long n2  = pk2(-2.0f, -2.0f);

    // ---- Phase 4: argmin over 256 pairs; STG zero store on iterations p<128.
    // Per lane: d = fma(-2, dot, add(sumx2, sE2[k])) — bit-identical to the
    // reference rounding, strict < gives lowest index on ties.
    float bestA = 3.4e38f, bestB = 3.4e38f;
    int   biA = 0, biB = 0;
    const float4 z4 = make_float4(0.f, 0.f, 0.f, 0.f);

#pragma unroll 2
    for (int p = 0; p < NPAIR; p++) {
        if (p < 128) zv[p * TPB + tid] = z4;   // LSU zero stream (front 0.75 MB)

        ulonglong2 v0 = sEp[p * 4 + 0];
        ulonglong2 v1 = sEp[p * 4 + 1];
        ulonglong2 v2 = sEp[p * 4 + 2];
        ulonglong2 v3 = sEp[p * 4 + 3];

        unsigned long long tA = mul2(xa[0], v0.x);
        unsigned long long tB = mul2(xb[0], v0.x);
        tA = fma2(xa[1], v0.y, tA);  tB = fma2(xb[1], v0.y, tB);
        tA = fma2(xa[2], v1.x, tA);  tB = fma2(xb[2], v1.x, tB);
        tA = fma2(xa[3], v1.y, tA);  tB = fma2(xb[3], v1.y, tB);
        tA = fma2(xa[4], v2.x, tA);  tB = fma2(xb[4], v2.x, tB);
        tA = fma2(xa[5], v2.y, tA);  tB = fma2(xb[5], v2.y, tB);
        tA = fma2(xa[6], v3.x, tA);  tB = fma2(xb[6], v3.x, tB);
        tA = fma2(xa[7], v3.y, tA);  tB = fma2(xb[7], v3.y, tB);

        unsigned long long e2 = *(const unsigned long long*)&sE2[2 * p];
        unsigned long long dA = fma2(n2, tA, add2(sA2, e2));
        unsigned long long dB = fma2(n2, tB, add2(sB2, e2));

        float dAl, dAh, dBl, dBh;
        upk2(dA, dAl, dAh);
        upk2(dB, dBl, dBh);
        if (dAl < bestA) { bestA = dAl; biA = 2 * p; }
        if (dAh < bestA) { bestA = dAh; biA = 2 * p + 1; }
        if (dBl < bestB) { bestB = dBl; biB = 2 * p; }
        if (dBh < bestB) { bestB = dBh; biB = 2 * p + 1; }
    }

    // ---- Phase 5: gather chosen entries, write quantized out, accumulate MSE
    const float* sf = (const float*)sEp;
    float acc = 0.0f;
    {
        int p = biA >> 1, l = biA & 1;
        float* op = out + O_OUT + (size_t)bb * (Dc * Sc) + sA;
#pragma unroll
        for (int c = 0; c < 8; c++) {
            float q = sf[p * 16 + (c >> 1) * 4 + (c & 1) * 2 + l];
            op[(size_t)c * Sc] = q;
            float dd = xA[c] - q;
            acc = fmaf(dd, dd, acc);
        }
    }
    {
        int p = biB >> 1, l = biB & 1;
        float* op = out + O_OUT + (size_t)bb * (Dc * Sc) + sB;
#pragma unroll
        for (int c = 0; c < 8; c++) {
            float q = sf[p * 16 + (c >> 1) * 4 + (c & 1) * 2 + l];
            op[(size_t)c * Sc] = q;
            float dd = xB[c] - q;
            acc = fmaf(dd, dd, acc);
        }
    }

    // ---- Phase 6: wait for TMA drain; barrier orders STG zeros too; scatter 1.0s
    if (tid < 8) asm volatile("cp.async.bulk.wait_group 0;" ::: "memory");
    __syncthreads();
    out[O_ENC + (size_t)n0 * Kc + biA] = 1.0f;
    out[O_ENC + (size_t)n1 * Kc + biB] = 1.0f;

    // ---- Phase 7: block-reduce squared error; last block finalizes the loss
#pragma unroll
    for (int o = 16; o > 0; o >>= 1) acc += __shfl_down_sync(0xFFFFFFFFu, acc, o);
    if ((tid & 31) == 0) sRed[tid >> 5] = acc;
    __syncthreads();
    if (tid == 0) {
        float v = 0.0f;
#pragma unroll
        for (int w = 0; w < TPB / 32; w++) v += sRed[w];
        atomicAdd(&g_sum, v);
        __threadfence();
        unsigned t = atomicAdd(&g_count, 1u);
        *sLast = (t == NBLK - 1) ? 1 : 0;
    }
    __syncthreads();
    if (*sLast && tid == 0) {
        float tot = *((volatile float*)&g_sum);
        float m = tot / (float)((size_t)Nc * Dc);
        m = fminf(fmaxf(m, 0.0f), 10.0f);
        out[0] = 1.25f * m;      // q_latent + BETA * e_latent (identical forward)
        g_sum = 0.0f;            // reset for next graph replay
        g_count = 0u;
    }
}

extern "C" void kernel_launch(void* const* d_in, const int* in_sizes, int n_in,
                              void* d_out, int out_size)
{
    const float* x  = (const float*)d_in[0];
    const float* ew = (const float*)d_in[1];
    float* out = (float*)d_out;

    cudaFuncSetAttribute(vq_main_kernel,
                         cudaFuncAttributeMaxDynamicSharedMemorySize, SMEM_TOTAL);
    vq_main_kernel<<<NBLK, TPB, SMEM_TOTAL>>>(x, ew, out);
}

// round 10
// speedup vs baseline: 1.3532x; 1.3532x over previous
#include <cuda_runtime.h>
#include <stdint.h>

// Problem constants (fixed shapes from reference)
#define Kc   512               // codebook size
#define Dc   8                 // embedding dim / channels
#define Sc   110592            // 48*48*48
#define Bc   2                 // batch
#define Nc   (Bc * Sc)         // 221184 voxels
#define TPB  256               // threads per block (8 warps)
#define VPB  512               // voxels per block (2 per thread)
#define NBLK (Nc / VPB)        // 432 blocks  (one wave @ 3 CTAs/SM)
#define NPAIR 256              // codebook pairs (Kc/2)
#define O_OUT 1                // out tensor offset (after scalar loss)
#define O_ENC (1 + Nc * Dc)    // encodings offset = 1769473
#define TILE_ENC (VPB * Kc)    // 262144 floats (1 MB) per block's tile
#define ZBUF_BYTES 24576       // 24 KB zero buffer (keeps static smem < 48 KB)

__device__ float    g_sum   = 0.0f;   // reset by last block each run
__device__ unsigned g_count = 0u;

// ---- packed f32x2 helpers (per-lane rounding identical to scalar chain) ----
__device__ __forceinline__ unsigned long long pk2(float lo, float hi) {
    unsigned long long r;
    asm("mov.b64 %0, {%1, %2};" : "=l"(r) : "f"(lo), "f"(hi));
    return r;
}
__device__ __forceinline__ unsigned long long mul2(unsigned long long a, unsigned long long b) {
    unsigned long long d;
    asm("mul.rn.f32x2 %0, %1, %2;" : "=l"(d) : "l"(a), "l"(b));
    return d;
}
__device__ __forceinline__ unsigned long long add2(unsigned long long a, unsigned long long b) {
    unsigned long long d;
    asm("add.rn.f32x2 %0, %1, %2;" : "=l"(d) : "l"(a), "l"(b));
    return d;
}
__device__ __forceinline__ unsigned long long fma2(unsigned long long a, unsigned long long b, unsigned long long c) {
    unsigned long long d;
    asm("fma.rn.f32x2 %0, %1, %2, %3;" : "=l"(d) : "l"(a), "l"(b), "l"(c));
    return d;
}
__device__ __forceinline__ void upk2(unsigned long long v, float& lo, float& hi) {
    asm("mov.b64 {%0, %1}, %2;" : "=f"(lo), "=f"(hi) : "l"(v));
}
__device__ __forceinline__ uint32_t smem_u32(const void* p) {
    uint32_t a;
    asm("{ .reg .u64 t; cvta.to.shared.u64 t, %1; cvt.u32.u64 %0, t; }" : "=r"(a) : "l"(p));
    return a;
}

__global__ __launch_bounds__(TPB, 3) void vq_main_kernel(
    const float* __restrict__ x,
    const float* __restrict__ ew,
    float* __restrict__ out)
{
    __shared__ float4     sZero[ZBUF_BYTES / 16];  // 24 KB zeros (TMA source)
    __shared__ ulonglong2 sEp[NPAIR * 4];          // 16 KB pair-packed codebook
    __shared__ float      sE2[Kc];                 // 2 KB entry sums of squares
    __shared__ float      sRed[TPB / 32];
    __shared__ int        sLast;
    // total static smem ~= 43 KB < 48 KB static limit; 3 CTAs/SM = 129 KB/SM.

    const int tid = threadIdx.x;

    // ---- Phase 0: fill 24 KB zero buffer (TMA source)
    {
        float4 z4 = make_float4(0.f, 0.f, 0.f, 0.f);
        for (int i = tid; i < ZBUF_BYTES / 16; i += TPB) sZero[i] = z4;
    }

    // ---- Phase 1a: build pair-packed codebook: pair p, coord c -> (e[2p][c], e[2p+1][c])
    {
        float* sf = (float*)sEp;
        for (int idx = tid; idx < NPAIR * Dc; idx += TPB) {
            int p = idx >> 3, c = idx & 7;
            float lo = ew[(2 * p) * Dc + c];
            float hi = ew[(2 * p + 1) * Dc + c];
            int base = p * 16 + (c >> 1) * 4 + (c & 1) * 2;
            sf[base]     = lo;
            sf[base + 1] = hi;
        }
    }
    // ---- Phase 1b: per-entry sum of squares, sequential fp32 (match jnp.sum(e**2))
    for (int k = tid; k < Kc; k += TPB) {
        float4 a = *(const float4*)(ew + (size_t)k * Dc);
        float4 b = *(const float4*)(ew + (size_t)k * Dc + 4);
        float s = __fmul_rn(a.x, a.x);
        s = __fadd_rn(s, __fmul_rn(a.y, a.y));
        s = __fadd_rn(s, __fmul_rn(a.z, a.z));
        s = __fadd_rn(s, __fmul_rn(a.w, a.w));
        s = __fadd_rn(s, __fmul_rn(b.x, b.x));
        s = __fadd_rn(s, __fmul_rn(b.y, b.y));
        s = __fadd_rn(s, __fmul_rn(b.z, b.z));
        s = __fadd_rn(s, __fmul_rn(b.w, b.w));
        sE2[k] = s;
    }
    // Make the generic-proxy smem zero writes visible to the async (TMA) proxy.
    asm volatile("fence.proxy.async.shared::cta;" ::: "memory");
    __syncthreads();

    // ---- Phase 2: zero-fill this block's 1 MB encodings tile: 44 x <=24 KB bulk
    // copies, spread over the first 8 lanes of warp 0.
    float* t0 = out + O_ENC + (size_t)blockIdx.x * TILE_ENC;
    const int head = (int)(((16u - (unsigned)(((uintptr_t)t0) & 15u)) & 15u) >> 2);
    if (tid < head) t0[tid] = 0.0f;                     // peel to 16B alignment
    const int nfl = (TILE_ENC - head) & ~3;             // floats covered by TMA
    const size_t nbytes = (size_t)nfl * 4;
    if (tid < 8) {
        uint32_t s_addr = smem_u32(sZero);
        char* g = (char*)(t0 + head);
        for (size_t off = (size_t)tid * ZBUF_BYTES; off < nbytes;
             off += (size_t)8 * ZBUF_BYTES) {
            unsigned sz = (unsigned)((nbytes - off) < (size_t)ZBUF_BYTES
                                     ? (nbytes - off) : (size_t)ZBUF_BYTES);
            asm volatile(
                "cp.async.bulk.global.shared::cta.bulk_group [%0], [%1], %2;"
                :: "l"(g + off), "r"(s_addr), "r"(sz) : "memory");
        }
        asm volatile("cp.async.bulk.commit_group;" ::: "memory");
    }
    {   // tail floats not covered by 16B-granular TMA
        int done = head + nfl;
        if (tid < TILE_ENC - done) t0[done + tid] = 0.0f;
    }

    // ---- Phase 3: load this thread's two voxels (strided, warp-coalesced)
    const int bb = (blockIdx.x * VPB) >= Sc ? 1 : 0;    // batch split is block-aligned
    const int n0 = blockIdx.x * VPB + tid;
    const int n1 = n0 + TPB;
    const int sA = n0 - bb * Sc;
    const int sB = n1 - bb * Sc;
    const float* xbase = x + (size_t)bb * (Dc * Sc);

    float xA[8], xB[8];
#pragma unroll
    for (int c = 0; c < 8; c++) {
        xA[c] = xbase[(size_t)c * Sc + sA];
        xB[c] = xbase[(size_t)c * Sc + sB];
    }
    unsigned long long xa[8], xb[8];
#pragma unroll
    for (int c = 0; c < 8; c++) { xa[c] = pk2(xA[c], xA[c]); xb[c] = pk2(xB[c], xB[c]); }

    float s2A = __fmul_rn(xA[0], xA[0]);
    float s2B = __fmul_rn(xB[0], xB[0]);
#pragma unroll
    for (int c = 1; c < 8; c++) {
        s2A = __fadd_rn(s2A, __fmul_rn(xA[c], xA[c]));
        s2B = __fadd_rn(s2B, __fmul_rn(xB[c], xB[c]));
    }
    const unsigned long long sA2 = pk2(s2A, s2A);
    const unsigned long long sB2 = pk2(s2B, s2B);
    const unsigned long long n2  = pk2(-2.0f, -2.0f);

    // ---- Phase 4: argmin over 256 pairs (pure FMA loop; TMA drains under it).
    // Per lane: d = fma(-2, dot, add(sumx2, sE2[k])) — bit-identical to the
    // reference rounding, strict < gives lowest index on ties.
    float bestA = 3.4e38f, bestB = 3.4e38f;
    int   biA = 0, biB = 0;

#pragma unroll 2
    for (int p = 0; p < NPAIR; p++) {
        ulonglong2 v0 = sEp[p * 4 + 0];
        ulonglong2 v1 = sEp[p * 4 + 1];
        ulonglong2 v2 = sEp[p * 4 + 2];
        ulonglong2 v3 = sEp[p * 4 + 3];

        unsigned long long tA = mul2(xa[0], v0.x);
        unsigned long long tB = mul2(xb[0], v0.x);
        tA = fma2(xa[1], v0.y, tA);  tB = fma2(xb[1], v0.y, tB);
        tA = fma2(xa[2], v1.x, tA);  tB = fma2(xb[2], v1.x, tB);
        tA = fma2(xa[3], v1.y, tA);  tB = fma2(xb[3], v1.y, tB);
        tA = fma2(xa[4], v2.x, tA);  tB = fma2(xb[4], v2.x, tB);
        tA = fma2(xa[5], v2.y, tA);  tB = fma2(xb[5], v2.y, tB);
        tA = fma2(xa[6], v3.x, tA);  tB = fma2(xb[6], v3.x, tB);
        tA = fma2(xa[7], v3.y, tA);  tB = fma2(xb[7], v3.y, tB);

        unsigned long long e2 = *(const unsigned long long*)&sE2[2 * p];
        unsigned long long dA = fma2(n2, tA, add2(sA2, e2));
        unsigned long long dB = fma2(n2, tB, add2(sB2, e2));

        float dAl, dAh, dBl, dBh;
        upk2(dA, dAl, dAh);
        upk2(dB, dBl, dBh);
        if (dAl < bestA) { bestA = dAl; biA = 2 * p; }
        if (dAh < bestA) { bestA = dAh; biA = 2 * p + 1; }
        if (dBl < bestB) { bestB = dBl; biB = 2 * p; }
        if (dBh < bestB) { bestB = dBh; biB = 2 * p + 1; }
    }

    // ---- Phase 5: gather chosen entries, write quantized out, accumulate MSE
    const float* sf = (const float*)sEp;
    float acc = 0.0f;
    {
        int p = biA >> 1, l = biA & 1;
        float* op = out + O_OUT + (size_t)bb * (Dc * Sc) + sA;
#pragma unroll
        for (int c = 0; c < 8; c++) {
            float q = sf[p * 16 + (c >> 1) * 4 + (c & 1) * 2 + l];
            op[(size_t)c * Sc] = q;
            float dd = xA[c] - q;
            acc = fmaf(dd, dd, acc);
        }
    }
    {
        int p = biB >> 1, l = biB & 1;
        float* op = out + O_OUT + (size_t)bb * (Dc * Sc) + sB;
#pragma unroll
        for (int c = 0; c < 8; c++) {
            float q = sf[p * 16 + (c >> 1) * 4 + (c & 1) * 2 + l];
            op[(size_t)c * Sc] = q;
            float dd = xB[c] - q;
            acc = fmaf(dd, dd, acc);
        }
    }

    // ---- Phase 6: wait for the TMA zero-fill, then scatter the 1.0s (WAW safe)
    if (tid < 8) asm volatile("cp.async.bulk.wait_group 0;" ::: "memory");
    __syncthreads();
    out[O_ENC + (size_t)n0 * Kc + biA] = 1.0f;
    out[O_ENC + (size_t)n1 * Kc + biB] = 1.0f;

    // ---- Phase 7: block-reduce squared error; last block finalizes the loss
#pragma unroll
    for (int o = 16; o > 0; o >>= 1) acc += __shfl_down_sync(0xFFFFFFFFu, acc, o);
    if ((tid & 31) == 0) sRed[tid >> 5] = acc;
    __syncthreads();
    if (tid == 0) {
        float v = 0.0f;
#pragma unroll
        for (int w = 0; w < TPB / 32; w++) v += sRed[w];
        atomicAdd(&g_sum, v);
        __threadfence();
        unsigned t = atomicAdd(&g_count, 1u);
        sLast = (t == NBLK - 1) ? 1 : 0;
    }
    __syncthreads();
    if (sLast && tid == 0) {
        float tot = *((volatile float*)&g_sum);
        float m = tot / (float)((size_t)Nc * Dc);
        m = fminf(fmaxf(m, 0.0f), 10.0f);
        out[0] = 1.25f * m;      // q_latent + BETA * e_latent (identical forward)
        g_sum = 0.0f;            // reset for next graph replay
        g_count = 0u;
    }
}

extern "C" void kernel_launch(void* const* d_in, const int* in_sizes, int n_in,
                              void* d_out, int out_size)
{
    const float* x  = (const float*)d_in[0];
    const float* ew = (const float*)d_in[1];
    float* out = (float*)d_out;

    vq_main_kernel<<<NBLK, TPB>>>(x, ew, out);
}

// round 11
// speedup vs baseline: 1.4788x; 1.0928x over previous
#include <cuda_runtime.h>
#include <stdint.h>

// Problem constants (fixed shapes from reference)
#define Kc   512               // codebook size
#define Dc   8                 // embedding dim / channels
#define Sc   110592            // 48*48*48
#define Bc   2                 // batch
#define Nc   (Bc * Sc)         // 221184 voxels
#define TPB  384               // threads per block (12 warps)
#define VPB  768               // voxels per block (2 per thread)
#define NBLK (Nc / VPB)        // 288 blocks  (one wave @ 2 CTAs/SM)
#define NPAIR 256              // codebook pairs (Kc/2)
#define O_OUT 1                // out tensor offset (after scalar loss)
#define O_ENC (1 + Nc * Dc)    // encodings offset = 1769473
#define TILE_ENC (VPB * Kc)    // 393216 floats (1.5 MB) per block's tile
#define ZBUF_BYTES 65536       // 64 KB smem zero buffer (TMA source)

// dynamic smem layout
#define SM_ZERO  0
#define SM_EP    (ZBUF_BYTES)                    // 16384 B pair-packed codebook
#define SM_E2    (ZBUF_BYTES + 16384)            // 2048 B entry sums of squares
#define SM_RED   (ZBUF_BYTES + 16384 + 2048)
#define SM_LAST  (SM_RED + 64)
#define SMEM_TOTAL (SM_LAST + 64)

__device__ float    g_sum   = 0.0f;   // reset by last block each run
__device__ unsigned g_count = 0u;

// ---- packed f32x2 helpers (per-lane rounding identical to scalar chain) ----
__device__ __forceinline__ unsigned long long pk2(float lo, float hi) {
    unsigned long long r;
    asm("mov.b64 %0, {%1, %2};" : "=l"(r) : "f"(lo), "f"(hi));
    return r;
}
__device__ __forceinline__ unsigned long long mul2(unsigned long long a, unsigned long long b) {
    unsigned long long d;
    asm("mul.rn.f32x2 %0, %1, %2;" : "=l"(d) : "l"(a), "l"(b));
    return d;
}
__device__ __forceinline__ unsigned long long add2(unsigned long long a, unsigned long long b) {
    unsigned long long d;
    asm("add.rn.f32x2 %0, %1, %2;" : "=l"(d) : "l"(a), "l"(b));
    return d;
}
__device__ __forceinline__ unsigned long long fma2(unsigned long long a, unsigned long long b, unsigned long long c) {
    unsigned long long d;
    asm("fma.rn.f32x2 %0, %1, %2, %3;" : "=l"(d) : "l"(a), "l"(b), "l"(c));
    return d;
}
__device__ __forceinline__ void upk2(unsigned long long v, float& lo, float& hi) {
    asm("mov.b64 {%0, %1}, %2;" : "=f"(lo), "=f"(hi) : "l"(v));
}
__device__ __forceinline__ uint32_t smem_u32(const void* p) {
    uint32_t a;
    asm("{ .reg .u64 t; cvta.to.shared.u64 t, %1; cvt.u32.u64 %0, t; }" : "=r"(a) : "l"(p));
    return a;
}

__global__ __launch_bounds__(TPB, 2) void vq_main_kernel(
    const float* __restrict__ x,
    const float* __restrict__ ew,
    float* __restrict__ out)
{
    extern __shared__ char smem[];
    float4*     sZero = (float4*)(smem + SM_ZERO);
    ulonglong2* sEp   = (ulonglong2*)(smem + SM_EP);   // pair-interleaved codebook
    float*      sE2   = (float*)(smem + SM_E2);
    float*      sRed  = (float*)(smem + SM_RED);
    int*        sLast = (int*)(smem + SM_LAST);

    const int tid = threadIdx.x;

    // ---- Phase 0: fill 64 KB zero buffer (TMA source)
    {
        float4 z4 = make_float4(0.f, 0.f, 0.f, 0.f);
        for (int i = tid; i < ZBUF_BYTES / 16; i += TPB) sZero[i] = z4;
    }

    // ---- Phase 1a: build pair-packed codebook: pair p, coord c -> (e[2p][c], e[2p+1][c])
    {
        float* sf = (float*)sEp;
        for (int idx = tid; idx < NPAIR * Dc; idx += TPB) {
            int p = idx >> 3, c = idx & 7;
            float lo = ew[(2 * p) * Dc + c];
            float hi = ew[(2 * p + 1) * Dc + c];
            int base = p * 16 + (c >> 1) * 4 + (c & 1) * 2;
            sf[base]     = lo;
            sf[base + 1] = hi;
        }
    }
    // ---- Phase 1b: per-entry sum of squares, sequential fp32 (match jnp.sum(e**2))
    for (int k = tid; k < Kc; k += TPB) {
        float4 a = *(const float4*)(ew + (size_t)k * Dc);
        float4 b = *(const float4*)(ew + (size_t)k * Dc + 4);
        float s = __fmul_rn(a.x, a.x);
        s = __fadd_rn(s, __fmul_rn(a.y, a.y));
        s = __fadd_rn(s, __fmul_rn(a.z, a.z));
        s = __fadd_rn(s, __fmul_rn(a.w, a.w));
        s = __fadd_rn(s, __fmul_rn(b.x, b.x));
        s = __fadd_rn(s, __fmul_rn(b.y, b.y));
        s = __fadd_rn(s, __fmul_rn(b.z, b.z));
        s = __fadd_rn(s, __fmul_rn(b.w, b.w));
        sE2[k] = s;
    }
    // Make the generic-proxy smem zero writes visible to the async (TMA) proxy.
    asm volatile("fence.proxy.async.shared::cta;" ::: "memory");
    __syncthreads();

    // ---- Phase 2: zero-fill this block's 1.5 MB tile: 24 x 64 KB bulk copies,
    // tagged L2::evict_first so the stream drains to DRAM instead of parking
    // dirty in L2 (kills the post-kernel writeback tail the harness pays for).
    float* t0 = out + O_ENC + (size_t)blockIdx.x * TILE_ENC;
    const int head = (int)(((16u - (unsigned)(((uintptr_t)t0) & 15u)) & 15u) >> 2);
    if (tid < head) t0[tid] = 0.0f;                     // peel to 16B alignment
    const int nfl = (TILE_ENC - head) & ~3;             // floats covered by TMA
    const size_t nbytes = (size_t)nfl * 4;
    if (tid < 8) {
        unsigned long long pol;
        asm("createpolicy.fractional.L2::evict_first.b64 %0, 1.0;" : "=l"(pol));
        uint32_t s_addr = smem_u32(sZero);
        char* g = (char*)(t0 + head);
        for (size_t off = (size_t)tid * ZBUF_BYTES; off < nbytes;
             off += (size_t)8 * ZBUF_BYTES) {
            unsigned sz = (unsigned)((nbytes - off) < (size_t)ZBUF_BYTES
                                     ? (nbytes - off) : (size_t)ZBUF_BYTES);
            asm volatile(
                "cp.async.bulk.global.shared::cta.bulk_group.L2::cache_hint "
                "[%0], [%1], %2, %3;"
                :: "l"(g + off), "r"(s_addr), "r"(sz), "l"(pol) : "memory");
        }
        asm volatile("cp.async.bulk.commit_group;" ::: "memory");
    }
    {   // tail floats not covered by 16B-granular TMA
        int done = head + nfl;
        if (tid < TILE_ENC - done) t0[done + tid] = 0.0f;
    }

    // ---- Phase 3: load this thread's two voxels (strided, warp-coalesced)
    const int bb = (blockIdx.x * VPB) >= Sc ? 1 : 0;    // batch split is block-aligned
    const int n0 = blockIdx.x * VPB + tid;
    const int n1 = n0 + TPB;
    const int sA = n0 - bb * Sc;
    const int sB = n1 - bb * Sc;
    const float* xbase = x + (size_t)bb * (Dc * Sc);

    float xA[8], xB[8];
#pragma unroll
    for (int c = 0; c < 8; c++) {
        xA[c] = xbase[(size_t)c * Sc + sA];
        xB[c] = xbase[(size_t)c * Sc + sB];
    }
    unsigned long long xa[8], xb[8];
#pragma unroll
    for (int c = 0; c < 8; c++) { xa[c] = pk2(xA[c], xA[c]); xb[c] = pk2(xB[c], xB[c]); }

    float s2A = __fmul_rn(xA[0], xA[0]);
    float s2B = __fmul_rn(xB[0], xB[0]);
#pragma unroll
    for (int c = 1; c < 8; c++) {
        s2A = __fadd_rn(s2A, __fmul_rn(xA[c], xA[c]));
        s2B = __fadd_rn(s2B, __fmul_rn(xB[c], xB[c]));
    }
    const unsigned long long sA2 = pk2(s2A, s2A);
    const unsigned long long sB2 = pk2(s2B, s2B);
    const unsigned long long n2  = pk2(-2.0f, -2.0f);

    // ---- Phase 4: argmin over 256 pairs (pure FMA loop; TMA drains under it).
    // Per lane: d = fma(-2, dot, add(sumx2, sE2[k])) — bit-identical to the
    // reference rounding, strict < gives lowest index on ties.
    float bestA = 3.4e38f, bestB = 3.4e38f;
    int   biA = 0, biB = 0;

#pragma unroll 2
    for (int p = 0; p < NPAIR; p++) {
        ulonglong2 v0 = sEp[p * 4 + 0];
        ulonglong2 v1 = sEp[p * 4 + 1];
        ulonglong2 v2 = sEp[p * 4 + 2];
        ulonglong2 v3 = sEp[p * 4 + 3];

        unsigned long long tA = mul2(xa[0], v0.x);
        unsigned long long tB = mul2(xb[0], v0.x);
        tA = fma2(xa[1], v0.y, tA);  tB = fma2(xb[1], v0.y, tB);
        tA = fma2(xa[2], v1.x, tA);  tB = fma2(xb[2], v1.x, tB);
        tA = fma2(xa[3], v1.y, tA);  tB = fma2(xb[3], v1.y, tB);
        tA = fma2(xa[4], v2.x, tA);  tB = fma2(xb[4], v2.x, tB);
        tA = fma2(xa[5], v2.y, tA);  tB = fma2(xb[5], v2.y, tB);
        tA = fma2(xa[6], v3.x, tA);  tB = fma2(xb[6], v3.x, tB);
        tA = fma2(xa[7], v3.y, tA);  tB = fma2(xb[7], v3.y, tB);

        unsigned long long e2 = *(const unsigned long long*)&sE2[2 * p];
        unsigned long long dA = fma2(n2, tA, add2(sA2, e2));
        unsigned long long dB = fma2(n2, tB, add2(sB2, e2));

        float dAl, dAh, dBl, dBh;
        upk2(dA, dAl, dAh);
        upk2(dB, dBl, dBh);
        if (dAl < bestA) { bestA = dAl; biA = 2 * p; }
        if (dAh < bestA) { bestA = dAh; biA = 2 * p + 1; }
        if (dBl < bestB) { bestB = dBl; biB = 2 * p; }
        if (dBh < bestB) { bestB = dBh; biB = 2 * p + 1; }
    }

    // ---- Phase 5: gather chosen entries, write quantized out (streaming),
    // accumulate MSE
    const float* sf = (const float*)sEp;
    float acc = 0.0f;
    {
        int p = biA >> 1, l = biA & 1;
        float* op = out + O_OUT + (size_t)bb * (Dc * Sc) + sA;
#pragma unroll
        for (int c = 0; c < 8; c++) {
            float q = sf[p * 16 + (c >> 1) * 4 + (c & 1) * 2 + l];
            __stcs(op + (size_t)c * Sc, q);
            float dd = xA[c] - q;
            acc = fmaf(dd, dd, acc);
        }
    }
    {
        int p = biB >> 1, l = biB & 1;
        float* op = out + O_OUT + (size_t)bb * (Dc * Sc) + sB;
#pragma unroll
        for (int c = 0; c < 8; c++) {
            float q = sf[p * 16 + (c >> 1) * 4 + (c & 1) * 2 + l];
            __stcs(op + (size_t)c * Sc, q);
            float dd = xB[c] - q;
            acc = fmaf(dd, dd, acc);
        }
    }

    // ---- Phase 6: wait for the TMA zero-fill, then scatter the 1.0s (WAW safe)
    if (tid < 8) asm volatile("cp.async.bulk.wait_group 0;" ::: "memory");
    __syncthreads();
    __stcs(out + O_ENC + (size_t)n0 * Kc + biA, 1.0f);
    __stcs(out + O_ENC + (size_t)n1 * Kc + biB, 1.0f);

    // ---- Phase 7: block-reduce squared error; last block finalizes the loss
#pragma unroll
    for (int o = 16; o > 0; o >>= 1) acc += __shfl_down_sync(0xFFFFFFFFu, acc, o);
    if ((tid & 31) == 0) sRed[tid >> 5] = acc;
    __syncthreads();
    if (tid == 0) {
        float v = 0.0f;
#pragma unroll
        for (int w = 0; w < TPB / 32; w++) v += sRed[w];
        atomicAdd(&g_sum, v);
        __threadfence();
        unsigned t = atomicAdd(&g_count, 1u);
        *sLast = (t == NBLK - 1) ? 1 : 0;
    }
    __syncthreads();
    if (*sLast && tid == 0) {
        float tot = *((volatile float*)&g_sum);
        float m = tot / (float)((size_t)Nc * Dc);
        m = fminf(fmaxf(m, 0.0f), 10.0f);
        out[0] = 1.25f * m;      // q_latent + BETA * e_latent (identical forward)
        g_sum = 0.0f;            // reset for next graph replay
        g_count = 0u;
    }
}

extern "C" void kernel_launch(void* const* d_in, const int* in_sizes, int n_in,
                              void* d_out, int out_size)
{
    const float* x  = (const float*)d_in[0];
    const float* ew = (const float*)d_in[1];
    float* out = (float*)d_out;

    cudaFuncSetAttribute(vq_main_kernel,
                         cudaFuncAttributeMaxDynamicSharedMemorySize, SMEM_TOTAL);
    vq_main_kernel<<<NBLK, TPB, SMEM_TOTAL>>>(x, ew, out);
}